// round 11
// baseline (speedup 1.0000x reference)
#include <cuda_runtime.h>
#include <math.h>
#include <stdint.h>

// Problem constants (B=2, S=4096 -> N=8192 tokens)
#define NTOK 8192
#define DDIM 2048
#define ENUM 8
#define FDIM 8192

// ---------------------------------------------------------------------------
// Device scratch (no allocations allowed -> __device__ globals)
// ---------------------------------------------------------------------------
__device__ float g_logits[NTOK * ENUM];          // [N, E] router logits
__device__ int   g_sel[2];                       // top-2 expert indices
__device__ float g_rw[NTOK * 2];                 // per-token softmax weights
__device__ float g_h[(size_t)NTOK * 2 * FDIM];   // [N, 2F]: rw-scaled hidden, tf32
__device__ float g_xr[(size_t)NTOK * DDIM];      // x rounded to tf32
__device__ float g_w1t[(size_t)2 * FDIM * DDIM]; // [slot][F][D] transposed tf32
__device__ float g_w2t[(size_t)DDIM * 2 * FDIM]; // [D][2F]      transposed tf32

// ---------------------------------------------------------------------------
// Helpers
// ---------------------------------------------------------------------------
__device__ __forceinline__ float to_tf32(float x) {
    uint32_t u;
    asm("cvt.rna.tf32.f32 %0, %1;" : "=r"(u) : "f"(x));
    return __uint_as_float(u);
}

__device__ __forceinline__ float gelu_tanh(float v) {
    const float c0 = 0.7978845608028654f;   // sqrt(2/pi)
    const float c1 = 0.044715f;
    float v3 = v * v * v;
    float t = tanhf(c0 * (v + c1 * v3));
    return 0.5f * v * (1.0f + t);
}

__device__ __forceinline__ void mma_tf32(float (&c)[4], const uint32_t (&a)[4],
                                         const uint32_t (&b)[2]) {
    asm volatile(
        "mma.sync.aligned.m16n8k8.row.col.f32.tf32.tf32.f32 "
        "{%0,%1,%2,%3}, {%4,%5,%6,%7}, {%8,%9}, {%0,%1,%2,%3};"
        : "+f"(c[0]), "+f"(c[1]), "+f"(c[2]), "+f"(c[3])
        : "r"(a[0]), "r"(a[1]), "r"(a[2]), "r"(a[3]), "r"(b[0]), "r"(b[1]));
}

#define LDSM4(r0, r1, r2, r3, a)                                             \
    asm volatile("ldmatrix.sync.aligned.m8n8.x4.shared.b16 {%0,%1,%2,%3}, [%4];" \
                 : "=r"(r0), "=r"(r1), "=r"(r2), "=r"(r3) : "r"(a))

// ---------------------------------------------------------------------------
// Router: logits[n][e] = dot(x[n], gate_w[e]); one warp per token (fp32 exact)
// ---------------------------------------------------------------------------
__global__ void router_kernel(const float* __restrict__ x,
                              const float* __restrict__ gw) {
    int warp = threadIdx.x >> 5;
    int lane = threadIdx.x & 31;
    int n = blockIdx.x * 8 + warp;
    if (n >= NTOK) return;

    const float4* xr = (const float4*)(x + (size_t)n * DDIM);
    float acc[ENUM];
#pragma unroll
    for (int e = 0; e < ENUM; e++) acc[e] = 0.0f;

    for (int i = lane; i < DDIM / 4; i += 32) {
        float4 xv = xr[i];
#pragma unroll
        for (int e = 0; e < ENUM; e++) {
            float4 gv = ((const float4*)(gw + (size_t)e * DDIM))[i];
            acc[e] += xv.x * gv.x + xv.y * gv.y + xv.z * gv.z + xv.w * gv.w;
        }
    }
#pragma unroll
    for (int e = 0; e < ENUM; e++) {
#pragma unroll
        for (int off = 16; off > 0; off >>= 1)
            acc[e] += __shfl_down_sync(0xFFFFFFFFu, acc[e], off);
    }
    if (lane == 0) {
#pragma unroll
        for (int e = 0; e < ENUM; e++)
            g_logits[(size_t)n * ENUM + e] = acc[e];
    }
}

// Fused per-expert column sum + top-2 select (deterministic fixed tree)
__global__ void colsum_select_kernel() {
    __shared__ float s[ENUM];
    int w = threadIdx.x >> 5;
    int lane = threadIdx.x & 31;
    float a = 0.0f;
    for (int n = lane; n < NTOK; n += 32)
        a += g_logits[(size_t)n * ENUM + w];
#pragma unroll
    for (int off = 16; off > 0; off >>= 1)
        a += __shfl_down_sync(0xFFFFFFFFu, a, off);
    if (lane == 0) s[w] = a;
    __syncthreads();
    if (threadIdx.x == 0) {
        float v0 = -INFINITY, v1 = -INFINITY;
        int b0 = 0, b1 = 0;
        for (int e = 0; e < ENUM; e++) {
            float v = s[e];
            if (v > v0) { v1 = v0; b1 = b0; v0 = v; b0 = e; }
            else if (v > v1) { v1 = v; b1 = e; }
        }
        g_sel[0] = b0;
        g_sel[1] = b1;
    }
}

// Per-token softmax over the two selected experts' logits
__global__ void rw_kernel() {
    int n = blockIdx.x * blockDim.x + threadIdx.x;
    if (n >= NTOK) return;
    int s0 = g_sel[0], s1 = g_sel[1];
    float l0 = g_logits[(size_t)n * ENUM + s0];
    float l1 = g_logits[(size_t)n * ENUM + s1];
    float m = fmaxf(l0, l1);
    float e0 = expf(l0 - m);
    float e1 = expf(l1 - m);
    float inv = 1.0f / (e0 + e1);
    g_rw[2 * n + 0] = e0 * inv;
    g_rw[2 * n + 1] = e1 * inv;
}

// ---------------------------------------------------------------------------
// Pre-passes: round x to tf32; transpose+round selected w1/w2 slices.
// ---------------------------------------------------------------------------
__global__ void round_copy(const float* __restrict__ src, float* __restrict__ dst,
                           int n4) {
    int i = blockIdx.x * blockDim.x + threadIdx.x;
    if (i >= n4) return;
    float4 v = ((const float4*)src)[i];
    v.x = to_tf32(v.x); v.y = to_tf32(v.y);
    v.z = to_tf32(v.z); v.w = to_tf32(v.w);
    ((float4*)dst)[i] = v;
}

// grid (256, 64, 4); z<2: w1[sel][d][f] -> w1t[slot][f][d]
//                    z>=2: w2[sel][f][d] -> w2t[d][slot*F + f]
__global__ void transpose_all(const float* __restrict__ w1,
                              const float* __restrict__ w2,
                              float* __restrict__ w1t, float* __restrict__ w2t) {
    __shared__ float t[32][33];
    const int z = blockIdx.z;
    const int slot = z & 1;
    const size_t perW = (size_t)DDIM * FDIM;
    const float* in;
    float* out;
    size_t inCols, outLd, outOff;
    int k0, n0;
    if (z < 2) {
        in = w1 + (size_t)g_sel[slot] * perW;
        inCols = FDIM;
        k0 = blockIdx.y * 32;       // d
        n0 = blockIdx.x * 32;       // f
        out = w1t + (size_t)slot * perW;
        outLd = DDIM;
        outOff = 0;
    } else {
        in = w2 + (size_t)g_sel[slot] * perW;
        inCols = DDIM;
        k0 = blockIdx.x * 32;       // f
        n0 = blockIdx.y * 32;       // d
        out = w2t;
        outLd = 2 * FDIM;
        outOff = (size_t)slot * FDIM;
    }
#pragma unroll
    for (int i = 0; i < 4; i++) {
        int k = k0 + threadIdx.y + i * 8;
        t[threadIdx.y + i * 8][threadIdx.x] = in[(size_t)k * inCols + n0 + threadIdx.x];
    }
    __syncthreads();
#pragma unroll
    for (int i = 0; i < 4; i++) {
        int n = n0 + threadIdx.y + i * 8;
        out[(size_t)n * outLd + outOff + k0 + threadIdx.x] =
            to_tf32(t[threadIdx.x][threadIdx.y + i * 8]);
    }
}

// ---------------------------------------------------------------------------
// tf32 tensor-core GEMM: 256x128x32 block tile, 16 warps (4x4), warp 64x32,
// m16n8k8 frags via ldmatrix.x4, 3-stage cp.async pipeline.
//   C = A[M,K] @ Bt[N,K]^T   (A row-major, Bt row-major N-by-K, tf32-rounded)
// MODE 0 (GEMM1): C[r, c] = to_tf32( rw[r][kslot] * gelu(acc + b1[sel][c]) )
// MODE 1 (GEMM2): C[r, c] = acc + rw[r][0]*b2[s0][c] + rw[r][1]*b2[s1][c]
// ---------------------------------------------------------------------------
#define BM 256
#define BN 128
#define BKT 32
#define SA 36                       // stride (floats): 144B -> LDSM conflict-free
#define ASZ (BM * SA)               // 9216 floats / stage
#define BSZ (BN * SA)               // 4608 floats / stage
#define STAGES 3
#define GEMM_SMEM ((ASZ + BSZ) * STAGES * 4)   // 165888 bytes
#define NTHR 512

template <int MODE>
__global__ void __launch_bounds__(NTHR, 1)
gemm_tf32(const float* __restrict__ A, const float* __restrict__ Bt,
          const float* __restrict__ b1v, const float* __restrict__ b2v,
          float* __restrict__ C, int N, int K, int ldc, int kslot) {
    extern __shared__ float smem[];

    const int tid = threadIdx.x;
    const int lane = tid & 31;
    const int warp = tid >> 5;
    const int mW = (warp >> 2) * 64;   // 4 warp-rows
    const int nW = (warp & 3) * 32;    // 4 warp-cols

    const float* Ap = A + (size_t)blockIdx.y * BM * K;
    const float* Bp = Bt + (size_t)blockIdx.x * BN * K;

    uint32_t sbase;
    asm("{ .reg .u64 t; cvta.to.shared.u64 t, %1; cvt.u32.u64 %0, t; }"
        : "=r"(sbase) : "l"(smem));

    float acc[4][4][4];
#pragma unroll
    for (int mf = 0; mf < 4; mf++)
#pragma unroll
        for (int nf = 0; nf < 4; nf++)
#pragma unroll
            for (int i = 0; i < 4; i++) acc[mf][nf][i] = 0.0f;

    const int NT = K / BKT;

    auto issue = [&](int kt) {
        int buf = kt % STAGES;
        float* Asm = smem + (size_t)buf * (ASZ + BSZ);
        float* Bsm = Asm + ASZ;
#pragma unroll
        for (int i = 0; i < 4; i++) {                    // A: 2048 x 16B
            int idx = tid + NTHR * i;
            int m = idx >> 3, kq = (idx & 7) * 4;
            uint32_t d = (uint32_t)__cvta_generic_to_shared(Asm + m * SA + kq);
            asm volatile("cp.async.cg.shared.global [%0], [%1], 16;"
                         :: "r"(d), "l"(Ap + (size_t)m * K + kt * BKT + kq));
        }
#pragma unroll
        for (int i = 0; i < 2; i++) {                    // B: 1024 x 16B
            int idx = tid + NTHR * i;
            int n = idx >> 3, kq = (idx & 7) * 4;
            uint32_t d = (uint32_t)__cvta_generic_to_shared(Bsm + n * SA + kq);
            asm volatile("cp.async.cg.shared.global [%0], [%1], 16;"
                         :: "r"(d), "l"(Bp + (size_t)n * K + kt * BKT + kq));
        }
        asm volatile("cp.async.commit_group;");
    };

    issue(0);
    if (NT > 1) issue(1);

    // ldmatrix per-thread selectors
    const int aRow = mW + (lane & 15);
    const int aCol = (lane >> 4) * 4;
    const int bRow = nW + (lane >> 4) * 8 + (lane & 7);
    const int bCol = ((lane >> 3) & 1) * 4;

#pragma unroll 1
    for (int kt = 0; kt < NT; kt++) {
        if (kt + 2 < NT) {
            issue(kt + 2);
            asm volatile("cp.async.wait_group 2;" ::: "memory");
        } else if (kt + 1 < NT) {
            asm volatile("cp.async.wait_group 1;" ::: "memory");
        } else {
            asm volatile("cp.async.wait_group 0;" ::: "memory");
        }
        __syncthreads();

        const uint32_t AsbA = sbase + (uint32_t)((kt % STAGES) * (ASZ + BSZ) * 4);
        const uint32_t BsbA = AsbA + ASZ * 4;

#pragma unroll
        for (int ks = 0; ks < 4; ks++) {
            uint32_t af[4][4];
            uint32_t bf[4][2];
#pragma unroll
            for (int mf = 0; mf < 4; mf++)
                LDSM4(af[mf][0], af[mf][1], af[mf][2], af[mf][3],
                      AsbA + (uint32_t)(((aRow + mf * 16) * SA + ks * 8 + aCol) * 4));
#pragma unroll
            for (int np = 0; np < 2; np++)
                LDSM4(bf[2 * np][0], bf[2 * np][1], bf[2 * np + 1][0], bf[2 * np + 1][1],
                      BsbA + (uint32_t)(((bRow + np * 16) * SA + ks * 8 + bCol) * 4));
#pragma unroll
            for (int mf = 0; mf < 4; mf++)
#pragma unroll
                for (int nf = 0; nf < 4; nf++)
                    mma_tf32(acc[mf][nf], af[mf], bf[nf]);
        }
        __syncthreads();
    }

    // --- epilogue (float2 vectorized stores) ---
    const int s0 = g_sel[0], s1 = g_sel[1];
    const int bNoff = blockIdx.x * BN;
    const float* bias1 = (MODE == 0) ? (b1v + (size_t)g_sel[kslot] * FDIM) : nullptr;
#pragma unroll
    for (int mf = 0; mf < 4; mf++) {
        int r0 = blockIdx.y * BM + mW + mf * 16 + (lane >> 2);
        int r1 = r0 + 8;
        float rwA0, rwA1, rwB0, rwB1;
        if (MODE == 0) {
            rwA0 = g_rw[r0 * 2 + kslot];
            rwB0 = g_rw[r1 * 2 + kslot];
            rwA1 = rwB1 = 0.0f;
        } else {
            rwA0 = g_rw[r0 * 2 + 0]; rwA1 = g_rw[r0 * 2 + 1];
            rwB0 = g_rw[r1 * 2 + 0]; rwB1 = g_rw[r1 * 2 + 1];
        }
#pragma unroll
        for (int nf = 0; nf < 4; nf++) {
            int c0 = bNoff + nW + nf * 8 + (lane & 3) * 2;
            float2* p0 = (float2*)(C + (size_t)r0 * ldc + c0);
            float2* p1 = (float2*)(C + (size_t)r1 * ldc + c0);
            if (MODE == 0) {
                float2 bv = *(const float2*)(bias1 + c0);
                float2 o0, o1;
                o0.x = to_tf32(rwA0 * gelu_tanh(acc[mf][nf][0] + bv.x));
                o0.y = to_tf32(rwA0 * gelu_tanh(acc[mf][nf][1] + bv.y));
                o1.x = to_tf32(rwB0 * gelu_tanh(acc[mf][nf][2] + bv.x));
                o1.y = to_tf32(rwB0 * gelu_tanh(acc[mf][nf][3] + bv.y));
                *p0 = o0;
                *p1 = o1;
            } else {
                float2 ba = *(const float2*)(b2v + (size_t)s0 * DDIM + c0);
                float2 bb = *(const float2*)(b2v + (size_t)s1 * DDIM + c0);
                float2 o0, o1;
                o0.x = acc[mf][nf][0] + rwA0 * ba.x + rwA1 * bb.x;
                o0.y = acc[mf][nf][1] + rwA0 * ba.y + rwA1 * bb.y;
                o1.x = acc[mf][nf][2] + rwB0 * ba.x + rwB1 * bb.x;
                o1.y = acc[mf][nf][3] + rwB0 * ba.y + rwB1 * bb.y;
                *p0 = o0;
                *p1 = o1;
            }
        }
    }
}

// ---------------------------------------------------------------------------
// Launch
// ---------------------------------------------------------------------------
extern "C" void kernel_launch(void* const* d_in, const int* in_sizes, int n_in,
                              void* d_out, int out_size) {
    (void)in_sizes; (void)n_in; (void)out_size;
    const float* x  = (const float*)d_in[0];  // [2,4096,2048]
    const float* gw = (const float*)d_in[1];  // [8,2048]
    const float* w1 = (const float*)d_in[2];  // [8,2048,8192]
    const float* b1 = (const float*)d_in[3];  // [8,8192]
    const float* w2 = (const float*)d_in[4];  // [8,8192,2048]
    const float* b2 = (const float*)d_in[5];  // [8,2048]
    float* out = (float*)d_out;               // [2,4096,2048]

    void* p;
    cudaGetSymbolAddress(&p, g_h);   float* h   = (float*)p;
    cudaGetSymbolAddress(&p, g_xr);  float* xr  = (float*)p;
    cudaGetSymbolAddress(&p, g_w1t); float* w1t = (float*)p;
    cudaGetSymbolAddress(&p, g_w2t); float* w2t = (float*)p;

    cudaFuncSetAttribute(gemm_tf32<0>, cudaFuncAttributeMaxDynamicSharedMemorySize, GEMM_SMEM);
    cudaFuncSetAttribute(gemm_tf32<1>, cudaFuncAttributeMaxDynamicSharedMemorySize, GEMM_SMEM);

    // Routing (exact fp32)                                        launches 1-3
    router_kernel<<<NTOK / 8, 256>>>(x, gw);
    colsum_select_kernel<<<1, 256>>>();
    rw_kernel<<<NTOK / 256, 256>>>();

    // Pre-passes                                                  launches 4-5
    const size_t perW = (size_t)DDIM * FDIM;
    const int n4x = NTOK * DDIM / 4;
    round_copy<<<(n4x + 255) / 256, 256>>>(x, xr, n4x);
    transpose_all<<<dim3(256, 64, 4), dim3(32, 8)>>>(w1, w2, w1t, w2t);

    // GEMM1 (x2): h[:, k*F:(k+1)*F] = to_tf32(rw[:,k]*gelu(x @ w1[sel_k] + b1))
    // launch 6 is gemm_tf32<0> slot 0 -> captured by ncu (-s 5 -c 1)
    dim3 g1(FDIM / BN, NTOK / BM);
    gemm_tf32<0><<<g1, NTHR, GEMM_SMEM>>>(xr, w1t,        b1, nullptr, h,
                                          FDIM, DDIM, 2 * FDIM, 0);
    gemm_tf32<0><<<g1, NTHR, GEMM_SMEM>>>(xr, w1t + perW, b1, nullptr, h + FDIM,
                                          FDIM, DDIM, 2 * FDIM, 1);

    // GEMM2 (single fused K=16384): out = h @ w2t^T + rw0*b2[s0] + rw1*b2[s1]
    dim3 g2(DDIM / BN, NTOK / BM);
    gemm_tf32<1><<<g2, NTHR, GEMM_SMEM>>>(h, w2t, nullptr, b2, out,
                                          DDIM, 2 * FDIM, DDIM, 0);
}

// round 12
// speedup vs baseline: 1.9289x; 1.9289x over previous
#include <cuda_runtime.h>
#include <cuda_fp16.h>
#include <math.h>
#include <stdint.h>

// Problem constants (B=2, S=4096 -> N=8192 tokens)
#define NTOK 8192
#define DDIM 2048
#define ENUM 8
#define FDIM 8192

// ---------------------------------------------------------------------------
// Device scratch (no allocations allowed -> __device__ globals)
// ---------------------------------------------------------------------------
__device__ float  g_logits[NTOK * ENUM];            // [N, E] router logits (fp32 exact)
__device__ int    g_sel[2];                         // top-2 expert indices
__device__ __half g_xh[(size_t)NTOK * DDIM];        // x in fp16
__device__ __half g_h[(size_t)NTOK * 2 * FDIM];     // [N, 2F] rw-scaled hidden, fp16
__device__ __half g_w1t[(size_t)2 * FDIM * DDIM];   // [slot][F][D] transposed fp16
__device__ __half g_w2t[(size_t)DDIM * 2 * FDIM];   // [D][2F]      transposed fp16

// ---------------------------------------------------------------------------
// Helpers
// ---------------------------------------------------------------------------
__device__ __forceinline__ float gelu_tanh(float v) {
    const float c0 = 0.7978845608028654f;   // sqrt(2/pi)
    const float c1 = 0.044715f;
    float v3 = v * v * v;
    float t = tanhf(c0 * (v + c1 * v3));
    return 0.5f * v * (1.0f + t);
}

// Per-token softmax weight over the two selected experts (matches reference)
__device__ __forceinline__ float2 rw_pair(int r) {
    float l0 = g_logits[(size_t)r * ENUM + g_sel[0]];
    float l1 = g_logits[(size_t)r * ENUM + g_sel[1]];
    float m = fmaxf(l0, l1);
    float e0 = expf(l0 - m);
    float e1 = expf(l1 - m);
    float inv = 1.0f / (e0 + e1);
    return make_float2(e0 * inv, e1 * inv);
}

__device__ __forceinline__ void mma_f16(float (&c)[4], const uint32_t (&a)[4],
                                        const uint32_t (&b)[2]) {
    asm volatile(
        "mma.sync.aligned.m16n8k16.row.col.f32.f16.f16.f32 "
        "{%0,%1,%2,%3}, {%4,%5,%6,%7}, {%8,%9}, {%0,%1,%2,%3};"
        : "+f"(c[0]), "+f"(c[1]), "+f"(c[2]), "+f"(c[3])
        : "r"(a[0]), "r"(a[1]), "r"(a[2]), "r"(a[3]), "r"(b[0]), "r"(b[1]));
}

#define LDSM4(r0, r1, r2, r3, a)                                             \
    asm volatile("ldmatrix.sync.aligned.m8n8.x4.shared.b16 {%0,%1,%2,%3}, [%4];" \
                 : "=r"(r0), "=r"(r1), "=r"(r2), "=r"(r3) : "r"(a))

// ---------------------------------------------------------------------------
// Router (+ x -> fp16 conversion fused): one warp per token, fp32-exact logits
// ---------------------------------------------------------------------------
__global__ void router_kernel(const float* __restrict__ x,
                              const float* __restrict__ gw) {
    int warp = threadIdx.x >> 5;
    int lane = threadIdx.x & 31;
    int n = blockIdx.x * 8 + warp;
    if (n >= NTOK) return;

    const float4* xr = (const float4*)(x + (size_t)n * DDIM);
    __half2* xh2 = (__half2*)(g_xh + (size_t)n * DDIM);
    float acc[ENUM];
#pragma unroll
    for (int e = 0; e < ENUM; e++) acc[e] = 0.0f;

    for (int i = lane; i < DDIM / 4; i += 32) {
        float4 xv = xr[i];
        xh2[2 * i + 0] = __floats2half2_rn(xv.x, xv.y);
        xh2[2 * i + 1] = __floats2half2_rn(xv.z, xv.w);
#pragma unroll
        for (int e = 0; e < ENUM; e++) {
            float4 gv = ((const float4*)(gw + (size_t)e * DDIM))[i];
            acc[e] += xv.x * gv.x + xv.y * gv.y + xv.z * gv.z + xv.w * gv.w;
        }
    }
#pragma unroll
    for (int e = 0; e < ENUM; e++) {
#pragma unroll
        for (int off = 16; off > 0; off >>= 1)
            acc[e] += __shfl_down_sync(0xFFFFFFFFu, acc[e], off);
    }
    if (lane == 0) {
#pragma unroll
        for (int e = 0; e < ENUM; e++)
            g_logits[(size_t)n * ENUM + e] = acc[e];
    }
}

// Fused per-expert column sum + top-2 select (deterministic fixed tree;
// stable descending ties->lower index, matches lax.top_k)
__global__ void colsum_select_kernel() {
    __shared__ float s[ENUM];
    int w = threadIdx.x >> 5;
    int lane = threadIdx.x & 31;
    float a = 0.0f;
    for (int n = lane; n < NTOK; n += 32)
        a += g_logits[(size_t)n * ENUM + w];
#pragma unroll
    for (int off = 16; off > 0; off >>= 1)
        a += __shfl_down_sync(0xFFFFFFFFu, a, off);
    if (lane == 0) s[w] = a;
    __syncthreads();
    if (threadIdx.x == 0) {
        float v0 = -INFINITY, v1 = -INFINITY;
        int b0 = 0, b1 = 0;
        for (int e = 0; e < ENUM; e++) {
            float v = s[e];
            if (v > v0) { v1 = v0; b1 = b0; v0 = v; b0 = e; }
            else if (v > v1) { v1 = v; b1 = e; }
        }
        g_sel[0] = b0;
        g_sel[1] = b1;
    }
}

// ---------------------------------------------------------------------------
// Transpose + fp16-round selected expert weights.
// grid (256, 64, 4); z<2: w1[sel][d][f] -> w1t[slot][f][d]
//                    z>=2: w2[sel][f][d] -> w2t[d][slot*F + f]
// ---------------------------------------------------------------------------
__global__ void transpose_all(const float* __restrict__ w1,
                              const float* __restrict__ w2,
                              __half* __restrict__ w1t, __half* __restrict__ w2t) {
    __shared__ float t[32][33];
    const int z = blockIdx.z;
    const int slot = z & 1;
    const size_t perW = (size_t)DDIM * FDIM;
    const float* in;
    __half* out;
    size_t inCols, outLd, outOff;
    int k0, n0;
    if (z < 2) {
        in = w1 + (size_t)g_sel[slot] * perW;
        inCols = FDIM;
        k0 = blockIdx.y * 32;       // d
        n0 = blockIdx.x * 32;       // f
        out = w1t + (size_t)slot * perW;
        outLd = DDIM;
        outOff = 0;
    } else {
        in = w2 + (size_t)g_sel[slot] * perW;
        inCols = DDIM;
        k0 = blockIdx.x * 32;       // f
        n0 = blockIdx.y * 32;       // d
        out = w2t;
        outLd = 2 * FDIM;
        outOff = (size_t)slot * FDIM;
    }
#pragma unroll
    for (int i = 0; i < 4; i++) {
        int k = k0 + threadIdx.y + i * 8;
        t[threadIdx.y + i * 8][threadIdx.x] = in[(size_t)k * inCols + n0 + threadIdx.x];
    }
    __syncthreads();
#pragma unroll
    for (int i = 0; i < 4; i++) {
        int n = n0 + threadIdx.y + i * 8;
        out[(size_t)n * outLd + outOff + k0 + threadIdx.x] =
            __float2half_rn(t[threadIdx.x][threadIdx.y + i * 8]);
    }
}

// ---------------------------------------------------------------------------
// fp16 tensor-core GEMM: 256x128x64 block tile, 8 warps (4x2), warp 64x64,
// m16n8k16 frags via ldmatrix.x4, 3-stage cp.async pipeline.
//   C = A[M,K] @ Bt[N,K]^T   (A, Bt row-major fp16, K contiguous)
// MODE 0 (GEMM1): h[r, colOff+c] = half( rw(r)[kslot] * gelu(acc + b1[sel][c]) )
// MODE 1 (GEMM2): out[r, c] = acc + rw0*b2[s0][c] + rw1*b2[s1][c]
// ---------------------------------------------------------------------------
#define BM 256
#define BN 128
#define BKH 64                      // K halves per stage (128B per row)
#define SAH 72                      // row stride in halves (144B, LDSM conflict-free)
#define ASZH (BM * SAH)             // 18432 halves / stage
#define BSZH (BN * SAH)             // 9216 halves / stage
#define STAGES 3
#define GEMM_SMEM ((ASZH + BSZH) * STAGES * 2)   // 165888 bytes

template <int MODE>
__global__ void __launch_bounds__(256, 1)
gemm_f16(const __half* __restrict__ A, const __half* __restrict__ Bt,
         const float* __restrict__ b1v, const float* __restrict__ b2v,
         void* __restrict__ Cv, int N, int K, int ldc, int kslot) {
    extern __shared__ __half smem[];

    const int tid = threadIdx.x;
    const int lane = tid & 31;
    const int warp = tid >> 5;
    const int mW = (warp >> 1) * 64;   // 4 warp-rows
    const int nW = (warp & 1) * 64;    // 2 warp-cols

    const __half* Ap = A + (size_t)blockIdx.y * BM * K;
    const __half* Bp = Bt + (size_t)blockIdx.x * BN * K;

    uint32_t sbase;
    asm("{ .reg .u64 t; cvta.to.shared.u64 t, %1; cvt.u32.u64 %0, t; }"
        : "=r"(sbase) : "l"(smem));

    float acc[4][8][4];
#pragma unroll
    for (int mf = 0; mf < 4; mf++)
#pragma unroll
        for (int nf = 0; nf < 8; nf++)
#pragma unroll
            for (int i = 0; i < 4; i++) acc[mf][nf][i] = 0.0f;

    const int NT = K / BKH;

    auto issue = [&](int kt) {
        int buf = kt % STAGES;
        __half* Asm = smem + (size_t)buf * (ASZH + BSZH);
        __half* Bsm = Asm + ASZH;
#pragma unroll
        for (int i = 0; i < 8; i++) {                    // A: 2048 x 16B
            int idx = tid + 256 * i;
            int m = idx >> 3, kq = (idx & 7) * 8;        // 8 halves = 16B
            uint32_t d = (uint32_t)__cvta_generic_to_shared(Asm + m * SAH + kq);
            asm volatile("cp.async.cg.shared.global [%0], [%1], 16;"
                         :: "r"(d), "l"(Ap + (size_t)m * K + kt * BKH + kq));
        }
#pragma unroll
        for (int i = 0; i < 4; i++) {                    // B: 1024 x 16B
            int idx = tid + 256 * i;
            int n = idx >> 3, kq = (idx & 7) * 8;
            uint32_t d = (uint32_t)__cvta_generic_to_shared(Bsm + n * SAH + kq);
            asm volatile("cp.async.cg.shared.global [%0], [%1], 16;"
                         :: "r"(d), "l"(Bp + (size_t)n * K + kt * BKH + kq));
        }
        asm volatile("cp.async.commit_group;");
    };

    issue(0);
    if (NT > 1) issue(1);

    // ldmatrix per-thread selectors (b16 tiles; addresses in halves)
    const int aRow = mW + (lane & 15);
    const int aColH = (lane >> 4) * 8;
    const int bRow = nW + (lane >> 4) * 8 + (lane & 7);
    const int bColH = ((lane >> 3) & 1) * 8;

#pragma unroll 1
    for (int kt = 0; kt < NT; kt++) {
        if (kt + 2 < NT) {
            issue(kt + 2);
            asm volatile("cp.async.wait_group 2;" ::: "memory");
        } else if (kt + 1 < NT) {
            asm volatile("cp.async.wait_group 1;" ::: "memory");
        } else {
            asm volatile("cp.async.wait_group 0;" ::: "memory");
        }
        __syncthreads();

        const uint32_t AsbA = sbase + (uint32_t)((kt % STAGES) * (ASZH + BSZH) * 2);
        const uint32_t BsbA = AsbA + ASZH * 2;

#pragma unroll
        for (int ks = 0; ks < 4; ks++) {                 // 4 x k16 per BKH=64
            uint32_t af[4][4];
            uint32_t bf[8][2];
#pragma unroll
            for (int mf = 0; mf < 4; mf++)
                LDSM4(af[mf][0], af[mf][1], af[mf][2], af[mf][3],
                      AsbA + (uint32_t)(((aRow + mf * 16) * SAH + ks * 16 + aColH) * 2));
#pragma unroll
            for (int np = 0; np < 4; np++)
                LDSM4(bf[2 * np][0], bf[2 * np][1], bf[2 * np + 1][0], bf[2 * np + 1][1],
                      BsbA + (uint32_t)(((bRow + np * 16) * SAH + ks * 16 + bColH) * 2));
#pragma unroll
            for (int mf = 0; mf < 4; mf++)
#pragma unroll
                for (int nf = 0; nf < 8; nf++)
                    mma_f16(acc[mf][nf], af[mf], bf[nf]);
        }
        __syncthreads();
    }

    // --- epilogue (rw softmax computed inline from logits) ---
    const int s0 = g_sel[0], s1 = g_sel[1];
    const int bNoff = blockIdx.x * BN;
    const float* bias1 = (MODE == 0) ? (b1v + (size_t)g_sel[kslot] * FDIM) : nullptr;
#pragma unroll
    for (int mf = 0; mf < 4; mf++) {
        int r0 = blockIdx.y * BM + mW + mf * 16 + (lane >> 2);
        int r1 = r0 + 8;
        float2 rwA = rw_pair(r0);
        float2 rwB = rw_pair(r1);
        float rwA0 = (MODE == 0) ? (kslot == 0 ? rwA.x : rwA.y) : rwA.x;
        float rwB0 = (MODE == 0) ? (kslot == 0 ? rwB.x : rwB.y) : rwB.x;
        float rwA1 = rwA.y, rwB1 = rwB.y;
#pragma unroll
        for (int nf = 0; nf < 8; nf++) {
            int c0 = bNoff + nW + nf * 8 + (lane & 3) * 2;
            if (MODE == 0) {
                __half* C = (__half*)Cv;
                float2 bv = *(const float2*)(bias1 + c0);
                __half2* p0 = (__half2*)(C + (size_t)r0 * ldc + c0);
                __half2* p1 = (__half2*)(C + (size_t)r1 * ldc + c0);
                *p0 = __floats2half2_rn(rwA0 * gelu_tanh(acc[mf][nf][0] + bv.x),
                                        rwA0 * gelu_tanh(acc[mf][nf][1] + bv.y));
                *p1 = __floats2half2_rn(rwB0 * gelu_tanh(acc[mf][nf][2] + bv.x),
                                        rwB0 * gelu_tanh(acc[mf][nf][3] + bv.y));
            } else {
                float* C = (float*)Cv;
                float2 ba = *(const float2*)(b2v + (size_t)s0 * DDIM + c0);
                float2 bb = *(const float2*)(b2v + (size_t)s1 * DDIM + c0);
                float2 o0, o1;
                o0.x = acc[mf][nf][0] + rwA0 * ba.x + rwA1 * bb.x;
                o0.y = acc[mf][nf][1] + rwA0 * ba.y + rwA1 * bb.y;
                o1.x = acc[mf][nf][2] + rwB0 * ba.x + rwB1 * bb.x;
                o1.y = acc[mf][nf][3] + rwB0 * ba.y + rwB1 * bb.y;
                *(float2*)(C + (size_t)r0 * ldc + c0) = o0;
                *(float2*)(C + (size_t)r1 * ldc + c0) = o1;
            }
        }
    }
}

// ---------------------------------------------------------------------------
// Launch
// ---------------------------------------------------------------------------
extern "C" void kernel_launch(void* const* d_in, const int* in_sizes, int n_in,
                              void* d_out, int out_size) {
    (void)in_sizes; (void)n_in; (void)out_size;
    const float* x  = (const float*)d_in[0];  // [2,4096,2048]
    const float* gw = (const float*)d_in[1];  // [8,2048]
    const float* w1 = (const float*)d_in[2];  // [8,2048,8192]
    const float* b1 = (const float*)d_in[3];  // [8,8192]
    const float* w2 = (const float*)d_in[4];  // [8,8192,2048]
    const float* b2 = (const float*)d_in[5];  // [8,2048]
    float* out = (float*)d_out;               // [2,4096,2048]

    void* p;
    cudaGetSymbolAddress(&p, g_xh);  __half* xh  = (__half*)p;
    cudaGetSymbolAddress(&p, g_h);   __half* h   = (__half*)p;
    cudaGetSymbolAddress(&p, g_w1t); __half* w1t = (__half*)p;
    cudaGetSymbolAddress(&p, g_w2t); __half* w2t = (__half*)p;

    cudaFuncSetAttribute(gemm_f16<0>, cudaFuncAttributeMaxDynamicSharedMemorySize, GEMM_SMEM);
    cudaFuncSetAttribute(gemm_f16<1>, cudaFuncAttributeMaxDynamicSharedMemorySize, GEMM_SMEM);

    const size_t perW = (size_t)DDIM * FDIM;

    // 1: router (+ x->fp16); 2: colsum+select; 3: weight transpose+round
    router_kernel<<<NTOK / 8, 256>>>(x, gw);
    colsum_select_kernel<<<1, 256>>>();
    transpose_all<<<dim3(256, 64, 4), dim3(32, 8)>>>(w1, w2, w1t, w2t);

    // 4 (ncu-captured): GEMM1 slot 0; 5: GEMM1 slot 1
    dim3 g1(FDIM / BN, NTOK / BM);
    gemm_f16<0><<<g1, 256, GEMM_SMEM>>>(xh, w1t,        b1, nullptr, h,
                                        FDIM, DDIM, 2 * FDIM, 0);
    gemm_f16<0><<<g1, 256, GEMM_SMEM>>>(xh, w1t + perW, b1, nullptr, h + FDIM,
                                        FDIM, DDIM, 2 * FDIM, 1);

    // 6: GEMM2 (single fused K=16384): out = h @ w2t^T + rw0*b2[s0] + rw1*b2[s1]
    dim3 g2(DDIM / BN, NTOK / BM);
    gemm_f16<1><<<g2, 256, GEMM_SMEM>>>(h, w2t, nullptr, b2, out,
                                        DDIM, 2 * FDIM, DDIM, 0);
}